// round 13
// baseline (speedup 1.0000x reference)
#include <cuda_runtime.h>
#include <cuda_bf16.h>
#include <cstdint>

#define IH 512
#define IW 512
#define OH 256
#define OW 256
#define NBC 128
#define SEG 8             // output rows per block
#define NSEG (OH / SEG)   // 32

__device__ __forceinline__ float ex2_fast(float a) {
    float r;
    asm("ex2.approx.ftz.f32 %0, %1;" : "=f"(r) : "f"(a));
    return r;
}
__device__ __forceinline__ uint32_t smem_u32(const void* p) {
    return (uint32_t)__cvta_generic_to_shared(p);
}

// Each lane owns TWO output columns (2g, 2g+1); loads input cols 4g..4g+3 as
// one float4 per row. Outputs staged in SMEM; at block end, three 8 KB
// cp.async.bulk stores push each stream contiguously to GMEM.
struct RS { float sA, vA, xA, sB, vB, xB; };

__global__ __launch_bounds__(128)
void conv_softargmax2d_kernel(const float* __restrict__ x,
                              const float* __restrict__ temp,
                              float* __restrict__ out)
{
    __shared__ __align__(16) float sx[SEG * OW];   // coordx tile (8 KB)
    __shared__ __align__(16) float sy[SEG * OW];   // coordy tile
    __shared__ __align__(16) float sr[SEG * OW];   // resp tile

    const int g    = threadIdx.x;               // output-pair index 0..127
    const int lane = g & 31;
    const int bc   = blockIdx.y;
    const int oy0  = blockIdx.x * SEG;
    const bool isL0    = (lane == 0);
    const bool hasLeft = (g > 0);

    // k = log2(e) / max(T, eps): one FMUL + one MUFU per exp
    const float k = __fdividef(1.4426950408889634f, fmaxf(__ldg(temp), 1e-8f));

    const float* __restrict__ xp = x + (size_t)bc * (IH * IW) + 4 * g;
    float* __restrict__ coordx = out + (size_t)bc * (2 * OH * OW);
    float* __restrict__ coordy = coordx + OH * OW;
    float* __restrict__ resp   = out + (size_t)NBC * (2 * OH * OW)
                                     + (size_t)bc * (OH * OW);

    auto rowsums = [&](float4 v, float xl) -> RS {
        float e0 = ex2_fast(v.x * k); float p0 = e0 * v.x;
        float e1 = ex2_fast(v.y * k); float p1 = e1 * v.y;
        float e2 = ex2_fast(v.z * k); float p2 = e2 * v.z;
        float e3 = ex2_fast(v.w * k); float p3 = e3 * v.w;
        float eL = __shfl_up_sync(0xffffffffu, e3, 1);
        float pL = __shfl_up_sync(0xffffffffu, p3, 1);
        float eX = hasLeft ? ex2_fast(xl * k) : 0.0f;   // branchless lane-0 fix
        float pX = eX * xl;
        if (isL0) { eL = eX; pL = pX; }                 // selp, no divergence
        RS r;
        r.sA = eL + e0 + e1;  r.vA = pL + p0 + p1;  r.xA = e1 - eL;
        r.sB = e1 + e2 + e3;  r.vB = p1 + p2 + p3;  r.xB = e3 - e1;
        return r;
    };

    // ---- prologue: carry sums for input row 2*oy0-1 (zero at image top) ----
    RS r0 = {0, 0, 0, 0, 0, 0};
    const float* p = xp + (size_t)(2 * oy0) * IW;
    if (oy0 > 0) {
        const float* pp = p - IW;
        float4 v = *(const float4*)pp;
        float xl = (isL0 && hasLeft) ? pp[-1] : 0.0f;
        r0 = rowsums(v, xl);
    }

    // preload first iteration's two rows
    float4 v1 = *(const float4*)p;
    float4 v2 = *(const float4*)(p + IW);
    float xl1 = 0.0f, xl2 = 0.0f;
    if (isL0 && hasLeft) { xl1 = p[-1]; xl2 = p[IW - 1]; }

    const float nx = 2.0f / (float)(IW - 1);
    const float ny = 2.0f / (float)(IH - 1);
    const float gxA = (float)(4 * g);
    const float gxB = (float)(4 * g + 2);
    float gyc = 2.0f * (float)oy0;
    int os = 2 * g;                              // smem row offset

    #pragma unroll 2
    for (int i = 0; i < SEG; ++i) {
        const float* pn = p + 2 * IW;
        const float* pc = (i + 1 < SEG) ? pn : p;
        float4 w1 = *(const float4*)pc;
        float4 w2 = *(const float4*)(pc + IW);
        float yl1 = 0.0f, yl2 = 0.0f;
        if (isL0 && hasLeft) { yl1 = pc[-1]; yl2 = pc[IW - 1]; }

        RS r1 = rowsums(v1, xl1);
        RS r2 = rowsums(v2, xl2);

        float SA  = r0.sA + r1.sA + r2.sA;
        float VA  = r0.vA + r1.vA + r2.vA;
        float SxA = r0.xA + r1.xA + r2.xA;
        float SyA = r2.sA - r0.sA;

        float SB  = r0.sB + r1.sB + r2.sB;
        float VB  = r0.vB + r1.vB + r2.vB;
        float SxB = r0.xB + r1.xB + r2.xB;
        float SyB = r2.sB - r0.sB;

        float riA = __fdividef(1.0f, SA + 1e-12f);
        float riB = __fdividef(1.0f, SB + 1e-12f);

        float2 cx = { fmaf(fmaf(SxA, riA, gxA), nx, -1.0f),
                      fmaf(fmaf(SxB, riB, gxB), nx, -1.0f) };
        float2 cy = { fmaf(fmaf(SyA, riA, gyc), ny, -1.0f),
                      fmaf(fmaf(SyB, riB, gyc), ny, -1.0f) };
        float2 rv = { VA * riA, VB * riB };

        *(float2*)&sx[os] = cx;
        *(float2*)&sy[os] = cy;
        *(float2*)&sr[os] = rv;

        r0 = r2;
        v1 = w1; v2 = w2; xl1 = yl1; xl2 = yl2;
        p = pn; os += OW; gyc += 2.0f;
    }

    // ---- bulk async store: 3 x 8 KB contiguous SMEM -> GMEM ----
    __syncthreads();
    asm volatile("fence.proxy.async.shared::cta;" ::: "memory");
    if (threadIdx.x == 0) {
        const int bytes = SEG * OW * (int)sizeof(float);   // 8192
        uint32_t a0 = smem_u32(sx), a1 = smem_u32(sy), a2 = smem_u32(sr);
        float* g0 = coordx + oy0 * OW;
        float* g1 = coordy + oy0 * OW;
        float* g2 = resp   + oy0 * OW;
        asm volatile("cp.async.bulk.global.shared::cta.bulk_group [%0], [%1], %2;"
                     :: "l"(g0), "r"(a0), "r"(bytes) : "memory");
        asm volatile("cp.async.bulk.global.shared::cta.bulk_group [%0], [%1], %2;"
                     :: "l"(g1), "r"(a1), "r"(bytes) : "memory");
        asm volatile("cp.async.bulk.global.shared::cta.bulk_group [%0], [%1], %2;"
                     :: "l"(g2), "r"(a2), "r"(bytes) : "memory");
        asm volatile("cp.async.bulk.commit_group;" ::: "memory");
        asm volatile("cp.async.bulk.wait_group 0;" ::: "memory");
    }
}

extern "C" void kernel_launch(void* const* d_in, const int* in_sizes, int n_in,
                              void* d_out, int out_size)
{
    const float* x = (const float*)d_in[0];
    const float* t = (const float*)d_in[1];
    if (n_in >= 2 && in_sizes[0] == 1) { x = (const float*)d_in[1]; t = (const float*)d_in[0]; }

    dim3 block(128);
    dim3 grid(NSEG, NBC);   // 32 x 128 = 4096 blocks
    conv_softargmax2d_kernel<<<grid, block>>>(x, t, (float*)d_out);
}

// round 14
// speedup vs baseline: 1.0014x; 1.0014x over previous
#include <cuda_runtime.h>
#include <cuda_bf16.h>

#define IH 512
#define IW 512
#define OH 256
#define OW 256
#define NBC 128
#define SEG 16            // output rows per block (halo overhead halved vs 8)
#define NSEG (OH / SEG)   // 16

__device__ __forceinline__ float ex2_fast(float a) {
    float r;
    asm("ex2.approx.ftz.f32 %0, %1;" : "=f"(r) : "f"(a));
    return r;
}

// Each lane owns TWO output columns (2g, 2g+1); loads input cols 4g..4g+3 as
// one float4 per row. 128-thread block covers the full 256-col output width.
// Left tap (col 4g-1) comes from lane-1's .w via shfl; lane0 of each warp
// loads it (the line is L1-hot from the neighboring warp's float4).
struct RS { float sA, vA, xA, sB, vB, xB; };

__global__ __launch_bounds__(128)
void conv_softargmax2d_kernel(const float* __restrict__ x,
                              const float* __restrict__ temp,
                              float* __restrict__ out)
{
    const int g    = threadIdx.x;               // output-pair index 0..127
    const int lane = g & 31;
    const int bc   = blockIdx.y;
    const int oy0  = blockIdx.x * SEG;
    const bool isL0    = (lane == 0);
    const bool hasLeft = (g > 0);

    // k = log2(e) / max(T, eps): one FMUL + one MUFU per exp
    const float k = __fdividef(1.4426950408889634f, fmaxf(__ldg(temp), 1e-8f));

    const float* __restrict__ xp = x + (size_t)bc * (IH * IW) + 4 * g;
    float* __restrict__ coordx = out + (size_t)bc * (2 * OH * OW);
    float* __restrict__ coordy = coordx + OH * OW;
    float* __restrict__ resp   = out + (size_t)NBC * (2 * OH * OW)
                                     + (size_t)bc * (OH * OW);

    // horizontal window sums for one input row, both output columns
    auto rowsums = [&](float4 v, float xl) -> RS {
        float e0 = ex2_fast(v.x * k); float p0 = e0 * v.x;
        float e1 = ex2_fast(v.y * k); float p1 = e1 * v.y;
        float e2 = ex2_fast(v.z * k); float p2 = e2 * v.z;
        float e3 = ex2_fast(v.w * k); float p3 = e3 * v.w;
        float eL = __shfl_up_sync(0xffffffffu, e3, 1);
        float pL = __shfl_up_sync(0xffffffffu, p3, 1);
        // branchless lane-0 fix (xl is 0 for lanes that never load it)
        float eX = hasLeft ? ex2_fast(xl * k) : 0.0f;
        float pX = eX * xl;
        if (isL0) { eL = eX; pL = pX; }          // selp, no divergence
        RS r;
        r.sA = eL + e0 + e1;  r.vA = pL + p0 + p1;  r.xA = e1 - eL;
        r.sB = e1 + e2 + e3;  r.vB = p1 + p2 + p3;  r.xB = e3 - e1;
        return r;
    };

    // ---- prologue: carry sums for input row 2*oy0-1 (zero at image top) ----
    RS r0 = {0, 0, 0, 0, 0, 0};
    const float* p = xp + (size_t)(2 * oy0) * IW;
    if (oy0 > 0) {
        const float* pp = p - IW;
        float4 v = *(const float4*)pp;
        float xl = (isL0 && hasLeft) ? pp[-1] : 0.0f;
        r0 = rowsums(v, xl);
    }

    // preload first iteration's two rows
    float4 v1 = *(const float4*)p;
    float4 v2 = *(const float4*)(p + IW);
    float xl1 = 0.0f, xl2 = 0.0f;
    if (isL0 && hasLeft) { xl1 = p[-1]; xl2 = p[IW - 1]; }

    const float nx = 2.0f / (float)(IW - 1);
    const float ny = 2.0f / (float)(IH - 1);
    const float gxA = (float)(4 * g);
    const float gxB = (float)(4 * g + 2);
    float gyc = 2.0f * (float)oy0;
    int o = oy0 * OW + 2 * g;

    #pragma unroll 2
    for (int i = 0; i < SEG; ++i) {
        // prefetch next iteration's rows (clamped on last iter; in-bounds)
        const float* pn = p + 2 * IW;
        const float* pc = (i + 1 < SEG) ? pn : p;
        float4 w1 = *(const float4*)pc;
        float4 w2 = *(const float4*)(pc + IW);
        float yl1 = 0.0f, yl2 = 0.0f;
        if (isL0 && hasLeft) { yl1 = pc[-1]; yl2 = pc[IW - 1]; }

        RS r1 = rowsums(v1, xl1);
        RS r2 = rowsums(v2, xl2);

        float SA  = r0.sA + r1.sA + r2.sA;
        float VA  = r0.vA + r1.vA + r2.vA;
        float SxA = r0.xA + r1.xA + r2.xA;
        float SyA = r2.sA - r0.sA;

        float SB  = r0.sB + r1.sB + r2.sB;
        float VB  = r0.vB + r1.vB + r2.vB;
        float SxB = r0.xB + r1.xB + r2.xB;
        float SyB = r2.sB - r0.sB;

        float riA = __fdividef(1.0f, SA + 1e-12f);
        float riB = __fdividef(1.0f, SB + 1e-12f);

        float2 cx = { fmaf(fmaf(SxA, riA, gxA), nx, -1.0f),
                      fmaf(fmaf(SxB, riB, gxB), nx, -1.0f) };
        float2 cy = { fmaf(fmaf(SyA, riA, gyc), ny, -1.0f),
                      fmaf(fmaf(SyB, riB, gyc), ny, -1.0f) };
        float2 rv = { VA * riA, VB * riB };

        *(float2*)&coordx[o] = cx;
        *(float2*)&coordy[o] = cy;
        *(float2*)&resp[o]   = rv;

        // roll: this iteration's bottom row becomes next iteration's top
        r0 = r2;
        v1 = w1; v2 = w2; xl1 = yl1; xl2 = yl2;
        p = pn; o += OW; gyc += 2.0f;
    }
}

extern "C" void kernel_launch(void* const* d_in, const int* in_sizes, int n_in,
                              void* d_out, int out_size)
{
    const float* x = (const float*)d_in[0];
    const float* t = (const float*)d_in[1];
    if (n_in >= 2 && in_sizes[0] == 1) { x = (const float*)d_in[1]; t = (const float*)d_in[0]; }

    dim3 block(128);
    dim3 grid(NSEG, NBC);   // 16 x 128 = 2048 blocks
    conv_softargmax2d_kernel<<<grid, block>>>(x, t, (float*)d_out);
}

// round 15
// speedup vs baseline: 1.0763x; 1.0748x over previous
#include <cuda_runtime.h>
#include <cuda_bf16.h>

#define IH 512
#define IW 512
#define OH 256
#define OW 256
#define NBC 128
#define SEG 8             // output rows per block
#define NSEG (OH / SEG)   // 32

// Each lane owns TWO output columns (2g, 2g+1); loads input cols 4g..4g+3 as
// one float4 per row. 128-thread block covers the full 256-col output width.
// Left tap (col 4g-1) comes from lane-1's .w via shfl; lane0 of each warp
// loads it (the line is L1-hot from the neighboring warp's float4).
struct RS { float sA, vA, xA, sB, vB, xB; };

__global__ __launch_bounds__(128)
void conv_softargmax2d_kernel(const float* __restrict__ x,
                              const float* __restrict__ temp,
                              float* __restrict__ out)
{
    const int g    = threadIdx.x;               // output-pair index 0..127
    const int lane = g & 31;
    const int bc   = blockIdx.y;
    const int oy0  = blockIdx.x * SEG;
    const bool isL0    = (lane == 0);
    const bool hasLeft = (g > 0);

    // k = log2(e) / max(T, eps): one FMUL + one MUFU per exp
    const float k = __fdividef(1.4426950408889634f, fmaxf(__ldg(temp), 1e-8f));

    const float* __restrict__ xp = x + (size_t)bc * (IH * IW) + 4 * g;
    float* __restrict__ coordx = out + (size_t)bc * (2 * OH * OW);
    float* __restrict__ coordy = coordx + OH * OW;
    float* __restrict__ resp   = out + (size_t)NBC * (2 * OH * OW)
                                     + (size_t)bc * (OH * OW);

    // horizontal window sums for one input row, both output columns
    auto rowsums = [&](float4 v, float xl) -> RS {
        float e0 = exp2f(v.x * k); float p0 = e0 * v.x;
        float e1 = exp2f(v.y * k); float p1 = e1 * v.y;
        float e2 = exp2f(v.z * k); float p2 = e2 * v.z;
        float e3 = exp2f(v.w * k); float p3 = e3 * v.w;
        float eL = __shfl_up_sync(0xffffffffu, e3, 1);
        float pL = __shfl_up_sync(0xffffffffu, p3, 1);
        // branchless lane-0 fix (xl is 0 for lanes that never load it)
        float eX = hasLeft ? exp2f(xl * k) : 0.0f;
        float pX = eX * xl;
        if (isL0) { eL = eX; pL = pX; }          // selp, no divergence
        RS r;
        r.sA = eL + e0 + e1;  r.vA = pL + p0 + p1;  r.xA = e1 - eL;
        r.sB = e1 + e2 + e3;  r.vB = p1 + p2 + p3;  r.xB = e3 - e1;
        return r;
    };

    // ---- prologue: carry sums for input row 2*oy0-1 (zero at image top) ----
    RS r0 = {0, 0, 0, 0, 0, 0};
    const float* p = xp + (size_t)(2 * oy0) * IW;
    if (oy0 > 0) {
        const float* pp = p - IW;
        float4 v = *(const float4*)pp;
        float xl = (isL0 && hasLeft) ? pp[-1] : 0.0f;
        r0 = rowsums(v, xl);
    }

    // preload first iteration's two rows
    float4 v1 = *(const float4*)p;
    float4 v2 = *(const float4*)(p + IW);
    float xl1 = 0.0f, xl2 = 0.0f;
    if (isL0 && hasLeft) { xl1 = p[-1]; xl2 = p[IW - 1]; }

    const float nx = 2.0f / (float)(IW - 1);
    const float ny = 2.0f / (float)(IH - 1);
    const float gxA = (float)(4 * g);
    const float gxB = (float)(4 * g + 2);
    float gyc = 2.0f * (float)oy0;
    int o = oy0 * OW + 2 * g;

    #pragma unroll 2
    for (int i = 0; i < SEG; ++i) {
        // prefetch next iteration's rows (clamped on last iter; in-bounds)
        const float* pn = p + 2 * IW;
        const float* pc = (i + 1 < SEG) ? pn : p;
        float4 w1 = *(const float4*)pc;
        float4 w2 = *(const float4*)(pc + IW);
        float yl1 = 0.0f, yl2 = 0.0f;
        if (isL0 && hasLeft) { yl1 = pc[-1]; yl2 = pc[IW - 1]; }

        RS r1 = rowsums(v1, xl1);
        RS r2 = rowsums(v2, xl2);

        float SA  = r0.sA + r1.sA + r2.sA;
        float VA  = r0.vA + r1.vA + r2.vA;
        float SxA = r0.xA + r1.xA + r2.xA;
        float SyA = r2.sA - r0.sA;

        float SB  = r0.sB + r1.sB + r2.sB;
        float VB  = r0.vB + r1.vB + r2.vB;
        float SxB = r0.xB + r1.xB + r2.xB;
        float SyB = r2.sB - r0.sB;

        float riA = __fdividef(1.0f, SA + 1e-12f);
        float riB = __fdividef(1.0f, SB + 1e-12f);

        float2 cx = { fmaf(fmaf(SxA, riA, gxA), nx, -1.0f),
                      fmaf(fmaf(SxB, riB, gxB), nx, -1.0f) };
        float2 cy = { fmaf(fmaf(SyA, riA, gyc), ny, -1.0f),
                      fmaf(fmaf(SyB, riB, gyc), ny, -1.0f) };
        float2 rv = { VA * riA, VB * riB };

        *(float2*)&coordx[o] = cx;
        *(float2*)&coordy[o] = cy;
        *(float2*)&resp[o]   = rv;

        // roll: this iteration's bottom row becomes next iteration's top
        r0 = r2;
        v1 = w1; v2 = w2; xl1 = yl1; xl2 = yl2;
        p = pn; o += OW; gyc += 2.0f;
    }
}

extern "C" void kernel_launch(void* const* d_in, const int* in_sizes, int n_in,
                              void* d_out, int out_size)
{
    const float* x = (const float*)d_in[0];
    const float* t = (const float*)d_in[1];
    if (n_in >= 2 && in_sizes[0] == 1) { x = (const float*)d_in[1]; t = (const float*)d_in[0]; }

    dim3 block(128);
    dim3 grid(NSEG, NBC);   // 32 x 128 = 4096 blocks
    conv_softargmax2d_kernel<<<grid, block>>>(x, t, (float*)d_out);
}